// round 17
// baseline (speedup 1.0000x reference)
#include <cuda_runtime.h>
#include <cuda_bf16.h>
#include <cstdint>

#define BATCH 2
#define SEQ   2048
#define EMB   2048
#define NH    16
#define HD    128
#define MROWS (BATCH * SEQ)   // 4096
#define NBH   (BATCH * NH)    // 32
#define NQB   (SEQ / 64)      // 32
#define NGRP  4
#define ZPG   (NBH / NGRP)    // 8 heads per group

typedef __nv_bfloat16 bf;

// ---------------- scratch (device globals; no allocation allowed) ----------------
__device__ float g_S[(size_t)NBH * SEQ * SEQ / 2];  // bf16 expm1(s), lower+diag: 268 MB
__device__ float g_N[(size_t)MROWS * EMB];          // raw PV numerator (fp32, 33 MB)
__device__ float g_z[NBH * SEQ];                    // causal row sums of exp(s)
__device__ float g_suf[NBH * NQB * HD];             // block suffix V sums
__device__ float g_bsum[NBH * NQB * HD];
__device__ float g_tot[NBH * HD];
__device__ float g_sufr[(size_t)NBH * SEQ * HD];    // row-granular suffix V (33 MB)
__device__ unsigned g_min_key;

// bf16 operands
__device__ bf g_xh[(size_t)MROWS * EMB], g_xl[(size_t)MROWS * EMB];
__device__ bf g_wqh[(size_t)EMB * EMB];
__device__ bf g_wkh[(size_t)EMB * EMB];
__device__ bf g_wvh[(size_t)EMB * EMB], g_wvl[(size_t)EMB * EMB];
__device__ bf g_woh[(size_t)EMB * EMB], g_wol[(size_t)EMB * EMB];
__device__ bf g_qh[(size_t)MROWS * EMB];
__device__ bf g_kh[(size_t)MROWS * EMB];
__device__ bf g_vh[(size_t)MROWS * EMB];

// ---------------- streams/events (host objects; static init, pre-checkpoint) -----
struct HxStreams {
    cudaStream_t s1, s2, s3;
    cudaEvent_t  eI, eX, eQK, eV, eWo;
    cudaEvent_t  eS[NGRP], ePV[NGRP], eF[NGRP];
    HxStreams() {
        cudaStreamCreateWithFlags(&s1, cudaStreamNonBlocking);
        cudaStreamCreateWithFlags(&s2, cudaStreamNonBlocking);
        cudaStreamCreateWithFlags(&s3, cudaStreamNonBlocking);
        cudaEventCreateWithFlags(&eI,  cudaEventDisableTiming);
        cudaEventCreateWithFlags(&eX,  cudaEventDisableTiming);
        cudaEventCreateWithFlags(&eQK, cudaEventDisableTiming);
        cudaEventCreateWithFlags(&eV,  cudaEventDisableTiming);
        cudaEventCreateWithFlags(&eWo, cudaEventDisableTiming);
        for (int g = 0; g < NGRP; g++) {
            cudaEventCreateWithFlags(&eS[g],  cudaEventDisableTiming);
            cudaEventCreateWithFlags(&ePV[g], cudaEventDisableTiming);
            cudaEventCreateWithFlags(&eF[g],  cudaEventDisableTiming);
        }
    }
};
static HxStreams g_hx;

// ---------------- ordered-float min key ------------------------------------------
__device__ __forceinline__ unsigned f2key(float f) {
    int i = __float_as_int(f);
    return (i >= 0) ? ((unsigned)i | 0x80000000u) : ~((unsigned)i);
}
__device__ __forceinline__ float key2f(unsigned k) {
    int i = (k & 0x80000000u) ? (int)(k & 0x7fffffffu) : (int)(~k);
    return __int_as_float(i);
}
__global__ void k_init() {
    const int i = blockIdx.x * 256 + threadIdx.x;
    if (i == 0) g_min_key = 0xFFFFFFFFu;
    if (i < NBH * SEQ) g_z[i] = 0.f;
    if (i < NBH * NQB * HD) g_bsum[i] = 0.f;
}

// ---------------- warp-level helpers (portable PTX, sm_80+) ----------------------
__device__ __forceinline__ uint32_t smem_u32(const void* p) {
    uint32_t a;
    asm("{ .reg .u64 t; cvta.to.shared.u64 t, %1; cvt.u32.u64 %0, t; }" : "=r"(a) : "l"(p));
    return a;
}
__device__ __forceinline__ void ldsm_x4(uint32_t* r, uint32_t addr) {
    asm volatile("ldmatrix.sync.aligned.m8n8.x4.shared.b16 {%0,%1,%2,%3}, [%4];"
                 : "=r"(r[0]), "=r"(r[1]), "=r"(r[2]), "=r"(r[3]) : "r"(addr));
}
__device__ __forceinline__ void ldsm_x2(uint32_t* r, uint32_t addr) {
    asm volatile("ldmatrix.sync.aligned.m8n8.x2.shared.b16 {%0,%1}, [%2];"
                 : "=r"(r[0]), "=r"(r[1]) : "r"(addr));
}
__device__ __forceinline__ void ldsm_x2t(uint32_t* r, uint32_t addr) {
    asm volatile("ldmatrix.sync.aligned.m8n8.x2.trans.shared.b16 {%0,%1}, [%2];"
                 : "=r"(r[0]), "=r"(r[1]) : "r"(addr));
}
__device__ __forceinline__ void mma16816(float* c, const uint32_t* a, const uint32_t* b) {
    asm volatile(
        "mma.sync.aligned.m16n8k16.row.col.f32.bf16.bf16.f32 "
        "{%0,%1,%2,%3}, {%4,%5,%6,%7}, {%8,%9}, {%0,%1,%2,%3};"
        : "+f"(c[0]), "+f"(c[1]), "+f"(c[2]), "+f"(c[3])
        : "r"(a[0]), "r"(a[1]), "r"(a[2]), "r"(a[3]), "r"(b[0]), "r"(b[1]));
}
__device__ __forceinline__ void cp16(uint32_t dst, const void* src) {
    asm volatile("cp.async.cg.shared.global [%0], [%1], 16;" :: "r"(dst), "l"(src));
}
__device__ __forceinline__ void cp_commit() { asm volatile("cp.async.commit_group;"); }
template<int N> __device__ __forceinline__ void cp_wait() {
    asm volatile("cp.async.wait_group %0;" :: "n"(N));
}
__device__ __forceinline__ void split8(const float4& f0, const float4& f1,
                                       uint4& h, uint4& l) {
    __nv_bfloat162 t, u;
    t.x = __float2bfloat16(f0.x); t.y = __float2bfloat16(f0.y); h.x = *(uint32_t*)&t;
    u.x = __float2bfloat16(f0.x - __bfloat162float(t.x));
    u.y = __float2bfloat16(f0.y - __bfloat162float(t.y)); l.x = *(uint32_t*)&u;
    t.x = __float2bfloat16(f0.z); t.y = __float2bfloat16(f0.w); h.y = *(uint32_t*)&t;
    u.x = __float2bfloat16(f0.z - __bfloat162float(t.x));
    u.y = __float2bfloat16(f0.w - __bfloat162float(t.y)); l.y = *(uint32_t*)&u;
    t.x = __float2bfloat16(f1.x); t.y = __float2bfloat16(f1.y); h.z = *(uint32_t*)&t;
    u.x = __float2bfloat16(f1.x - __bfloat162float(t.x));
    u.y = __float2bfloat16(f1.y - __bfloat162float(t.y)); l.z = *(uint32_t*)&u;
    t.x = __float2bfloat16(f1.z); t.y = __float2bfloat16(f1.w); h.w = *(uint32_t*)&t;
    u.x = __float2bfloat16(f1.z - __bfloat162float(t.x));
    u.y = __float2bfloat16(f1.w - __bfloat162float(t.y)); l.w = *(uint32_t*)&u;
}

// ---------------- conversion kernels ---------------------------------------------
__global__ void k_split(const float* __restrict__ in,
                        bf* __restrict__ hi, bf* __restrict__ lo)
{
    size_t i = ((size_t)blockIdx.x * 256 + threadIdx.x) * 8;
    float4 f0 = *(const float4*)(in + i);
    float4 f1 = *(const float4*)(in + i + 4);
    uint4 h, l;
    split8(f0, f1, h, l);
    *(uint4*)(hi + i) = h;
    if (lo) *(uint4*)(lo + i) = l;
}

__global__ void k_splitwT(const float* __restrict__ W,
                          bf* __restrict__ Th, bf* __restrict__ Tl)
{
    __shared__ float t[32][33];
    const int tx = threadIdx.x, ty = threadIdx.y;
    const int n0 = blockIdx.x * 32, k0 = blockIdx.y * 32;
#pragma unroll
    for (int i = ty; i < 32; i += 8)
        t[i][tx] = W[(size_t)(k0 + i) * EMB + n0 + tx];
    __syncthreads();
#pragma unroll
    for (int i = ty; i < 32; i += 8) {
        float v = t[tx][i];
        bf h = __float2bfloat16(v);
        Th[(size_t)(n0 + i) * EMB + k0 + tx] = h;
        if (Tl)
            Tl[(size_t)(n0 + i) * EMB + k0 + tx] = __float2bfloat16(v - __bfloat162float(h));
    }
}

// ---------------- HMMA GEMM (cp.async pipelined) ----------------------------------
// NPROD=3: Ah*Bh + Ah*Bl + Al*Bh (chunk 32, 2 stages); NPROD=1: Ah*Bh (chunk 64, 3 st).
// modes: 3 = fp32 + bias; 4 = bf16 out (gridDim.z==2 merged via Bhi2/outB2);
//        6 = scores: bf16 expm1 store (skip strictly-upper), Z atomics, global min;
//        7 = bf16 out + per-64-row-block column sums into g_bsum.
#define MMA_PL32 10240
#define MMA_PL64 18432
template<int NPROD>
__global__ __launch_bounds__(256, 2) void k_mma_t(
    const bf* __restrict__ Ahi, const bf* __restrict__ Alo,
    const bf* __restrict__ Bhi, const bf* __restrict__ Blo,
    int lda, int ldb, int K, int mode, int zb,
    float* __restrict__ outF, bf* __restrict__ outB,
    const float* __restrict__ bias,
    const bf* __restrict__ Bhi2, bf* __restrict__ outB2)
{
    constexpr int CHUNK   = (NPROD == 3) ? 32 : 64;
    constexpr int STAGES  = (NPROD == 3) ? 2 : 3;
    constexpr int PLANE   = (NPROD == 3) ? MMA_PL32 : MMA_PL64;
    constexpr int STAGEB  = (NPROD == 3) ? 4 * MMA_PL32 : 2 * MMA_PL64;
    constexpr int PB      = (NPROD == 3) ? 2 * MMA_PL32 : MMA_PL64;
    constexpr int RSTRIDE = (NPROD == 3) ? 80 : 144;
    extern __shared__ char dsm[];
    __shared__ float s_redmin[8];
    const uint32_t sb = smem_u32(dsm);

    const int tid  = threadIdx.x;
    const int wid  = tid >> 5;
    const int lane = tid & 31;

    size_t aOff = 0, bOff = 0, cOff = 0;
    int zg = 0;
    const bf* Bsel = Bhi;
    bf* oBsel = outB;
    if (mode == 6) {
        zg = zb + blockIdx.z;
        const int b = zg >> 4, h = zg & 15;
        aOff = (size_t)b * SEQ * lda + h * HD;
        bOff = (size_t)b * SEQ * ldb + h * HD;
        cOff = (size_t)zg * SEQ * SEQ;
    } else if (mode == 4 && blockIdx.z == 1) {
        Bsel = Bhi2;
        oBsel = outB2;
    }
    const size_t mrow0 = (size_t)blockIdx.y * 128;
    const int    ncol0 = blockIdx.x * 128;

    auto issue = [&](int ci) {
        const int c = ci * CHUNK;
        const uint32_t so = sb + (ci % STAGES) * STAGEB;
        if (NPROD == 1) {
#pragma unroll
            for (int l = 0; l < 4; l++) {
                const int v = tid + l * 256;
                const int r = v >> 3, ce = (v & 7) * 8;
                cp16(so + r * 144 + ce * 2,
                     Ahi + aOff + (mrow0 + r) * (size_t)lda + c + ce);
                cp16(so + PB + r * 144 + ce * 2,
                     Bsel + bOff + (size_t)(ncol0 + r) * ldb + c + ce);
            }
        } else {
            const int r0 = tid >> 2, r1 = r0 + 64;
            const int cg = (tid & 3) * 8;
            const uint32_t cgB = (tid & 3) * 16;
            const size_t a0 = aOff + (mrow0 + r0) * (size_t)lda + c + cg;
            const size_t a1 = aOff + (mrow0 + r1) * (size_t)lda + c + cg;
            const size_t b0 = bOff + (size_t)(ncol0 + r0) * ldb + c + cg;
            const size_t b1 = bOff + (size_t)(ncol0 + r1) * ldb + c + cg;
            cp16(so + r0 * 80 + cgB, Ahi + a0);
            cp16(so + r1 * 80 + cgB, Ahi + a1);
            cp16(so + PB + r0 * 80 + cgB, Bsel + b0);
            cp16(so + PB + r1 * 80 + cgB, Bsel + b1);
            cp16(so + PLANE + r0 * 80 + cgB, Alo + a0);
            cp16(so + PLANE + r1 * 80 + cgB, Alo + a1);
            cp16(so + 3 * PLANE + r0 * 80 + cgB, Blo + b0);
            cp16(so + 3 * PLANE + r1 * 80 + cgB, Blo + b1);
        }
    };

    const int m0 = (wid >> 2) * 64;
    const int n0 = (wid & 3) * 32;
    const int alr = lane & 15;
    const int alc = (lane >> 4) * 8;
    const int l15 = lane & 15;
    const int blr = l15 & 7;
    const int blc = (l15 >> 3) * 8;

    float acc[4][4][4];
#pragma unroll
    for (int i = 0; i < 4; i++)
#pragma unroll
        for (int j = 0; j < 4; j++)
#pragma unroll
            for (int c = 0; c < 4; c++) acc[i][j][c] = 0.f;

    const int nchunks = K / CHUNK;
#pragma unroll
    for (int s = 0; s < STAGES - 1; s++) {
        if (s < nchunks) issue(s);
        cp_commit();
    }
    for (int ci = 0; ci < nchunks; ci++) {
        cp_wait<STAGES - 2>();
        __syncthreads();
        if (ci + STAGES - 1 < nchunks) issue(ci + STAGES - 1);
        cp_commit();

        const uint32_t so  = sb + (ci % STAGES) * STAGEB;
        const uint32_t pAh = so;
        const uint32_t pAl = so + PLANE;
        const uint32_t pBh = so + PB;
        const uint32_t pBl = so + 3 * PLANE;
#pragma unroll
        for (int ks = 0; ks < CHUNK; ks += 16) {
            uint32_t fAh[4][4], fAl[4][4], fBh[4][2], fBl[4][2];
#pragma unroll
            for (int i = 0; i < 4; i++) {
                ldsm_x4(fAh[i], pAh + (m0 + 16 * i + alr) * RSTRIDE + (ks + alc) * 2);
                if (NPROD == 3)
                    ldsm_x4(fAl[i], pAl + (m0 + 16 * i + alr) * RSTRIDE + (ks + alc) * 2);
            }
#pragma unroll
            for (int j = 0; j < 4; j++) {
                ldsm_x2(fBh[j], pBh + (n0 + 8 * j + blr) * RSTRIDE + (ks + blc) * 2);
                if (NPROD == 3)
                    ldsm_x2(fBl[j], pBl + (n0 + 8 * j + blr) * RSTRIDE + (ks + blc) * 2);
            }
#pragma unroll
            for (int i = 0; i < 4; i++)
#pragma unroll
                for (int j = 0; j < 4; j++) {
                    mma16816(acc[i][j], fAh[i], fBh[j]);
                    if (NPROD == 3) {
                        mma16816(acc[i][j], fAh[i], fBl[j]);
                        mma16816(acc[i][j], fAl[i], fBh[j]);
                    }
                }
        }
    }

    // ---- epilogue ----
    const int g  = lane >> 2;
    const int t2 = (lane & 3) * 2;
    if (mode == 3) {
#pragma unroll
        for (int i = 0; i < 4; i++) {
#pragma unroll
            for (int j = 0; j < 4; j++) {
                const size_t gr = mrow0 + m0 + 16 * i + g;
                const int    gc = ncol0 + n0 + 8 * j + t2;
                const float b0v = bias[gc], b1v = bias[gc + 1];
                float2 v0 = {acc[i][j][0] + b0v, acc[i][j][1] + b1v};
                float2 v1 = {acc[i][j][2] + b0v, acc[i][j][3] + b1v};
                *(float2*)(outF + gr * EMB + gc)       = v0;
                *(float2*)(outF + (gr + 8) * EMB + gc) = v1;
            }
        }
    } else if (mode == 6) {
        bf* Sz = outB + cOff;
        const bool skipStore = (ncol0 > (int)mrow0);
        float vmin = 3.0e38f;
        float zacc[4][2];
#pragma unroll
        for (int i = 0; i < 4; i++) { zacc[i][0] = 0.f; zacc[i][1] = 0.f; }
#pragma unroll
        for (int i = 0; i < 4; i++) {
            const int gr = (int)mrow0 + m0 + 16 * i + g;
#pragma unroll
            for (int j = 0; j < 4; j++) {
                const int gc = ncol0 + n0 + 8 * j + t2;
                const float e0 = __expf(acc[i][j][0]), e1 = __expf(acc[i][j][1]);
                const float e2 = __expf(acc[i][j][2]), e3 = __expf(acc[i][j][3]);
                const float u0 = e0 - 1.f, u1 = e1 - 1.f;
                const float u2 = e2 - 1.f, u3 = e3 - 1.f;
                vmin = fminf(vmin, fminf(fminf(u0, u1), fminf(u2, u3)));
                if (!skipStore) {
                    __nv_bfloat162 p;
                    p.x = __float2bfloat16(u0); p.y = __float2bfloat16(u1);
                    *(__nv_bfloat162*)(Sz + (size_t)gr * SEQ + gc) = p;
                    p.x = __float2bfloat16(u2); p.y = __float2bfloat16(u3);
                    *(__nv_bfloat162*)(Sz + (size_t)(gr + 8) * SEQ + gc) = p;
                    zacc[i][0] += (gc <= gr ? e0 : 0.f) + (gc + 1 <= gr ? e1 : 0.f);
                    zacc[i][1] += (gc <= gr + 8 ? e2 : 0.f) + (gc + 1 <= gr + 8 ? e3 : 0.f);
                }
            }
        }
        if (!skipStore) {
#pragma unroll
            for (int i = 0; i < 4; i++) {
#pragma unroll
                for (int hh = 0; hh < 2; hh++) {
                    float v = zacc[i][hh];
                    v += __shfl_xor_sync(0xffffffffu, v, 1);
                    v += __shfl_xor_sync(0xffffffffu, v, 2);
                    if ((lane & 3) == 0 && v > 0.f)
                        atomicAdd(&g_z[(size_t)zg * SEQ + mrow0 + m0 + 16 * i + g + hh * 8], v);
                }
            }
        }
#pragma unroll
        for (int off = 16; off; off >>= 1)
            vmin = fminf(vmin, __shfl_xor_sync(0xffffffffu, vmin, off));
        if (lane == 0) s_redmin[wid] = vmin;
        __syncthreads();
        if (tid == 0) {
            float m = s_redmin[0];
#pragma unroll
            for (int w = 1; w < 8; w++) m = fminf(m, s_redmin[w]);
            atomicMin(&g_min_key, f2key(m));
        }
    } else {  // mode 4 or 7
#pragma unroll
        for (int i = 0; i < 4; i++) {
#pragma unroll
            for (int j = 0; j < 4; j++) {
                const size_t gr = mrow0 + m0 + 16 * i + g;
                const int    gc = ncol0 + n0 + 8 * j + t2;
                __nv_bfloat162 h;
                h.x = __float2bfloat16(acc[i][j][0]); h.y = __float2bfloat16(acc[i][j][1]);
                *(__nv_bfloat162*)(oBsel + gr * EMB + gc) = h;
                h.x = __float2bfloat16(acc[i][j][2]); h.y = __float2bfloat16(acc[i][j][3]);
                *(__nv_bfloat162*)(oBsel + (gr + 8) * EMB + gc) = h;
            }
        }
        if (mode == 7) {
#pragma unroll
            for (int j = 0; j < 4; j++) {
                float c0 = 0.f, c1 = 0.f;
#pragma unroll
                for (int i = 0; i < 4; i++) {
                    c0 += acc[i][j][0] + acc[i][j][2];
                    c1 += acc[i][j][1] + acc[i][j][3];
                }
                c0 += __shfl_xor_sync(0xffffffffu, c0, 4);
                c1 += __shfl_xor_sync(0xffffffffu, c1, 4);
                c0 += __shfl_xor_sync(0xffffffffu, c0, 8);
                c1 += __shfl_xor_sync(0xffffffffu, c1, 8);
                c0 += __shfl_xor_sync(0xffffffffu, c0, 16);
                c1 += __shfl_xor_sync(0xffffffffu, c1, 16);
                if (lane < 4) {
                    const int grow = (int)mrow0 + m0;
                    const int bb = grow >> 11, sr = grow & 2047, kb = sr >> 6;
                    const int gc = ncol0 + n0 + 8 * j + t2;
                    atomicAdd(&g_bsum[(((size_t)(bb * 16 + (gc >> 7)) * NQB) + kb) * HD + (gc & 127)], c0);
                    const int gc1 = gc + 1;
                    atomicAdd(&g_bsum[(((size_t)(bb * 16 + (gc1 >> 7)) * NQB) + kb) * HD + (gc1 & 127)], c1);
                }
            }
        }
    }
}
#define MMA_SMEM_3 (2 * 4 * MMA_PL32)    // 81920
#define MMA_SMEM_1 (3 * 2 * MMA_PL64)    // 110592

// ---------------- suffix scan over block sums ------------------------------------
__global__ void k_sufv2()
{
    const int z = blockIdx.x;
    const int d = threadIdx.x;
    float acc = 0.f;
    for (int kb = NQB - 1; kb >= 0; kb--) {
        g_suf[((size_t)z * NQB + kb) * HD + d] = acc;
        acc += g_bsum[((size_t)z * NQB + kb) * HD + d];
    }
    g_tot[z * HD + d] = acc;
}

// ---------------- row-granular V suffix: sufr[i] = sum_{j>i} V_j ------------------
__global__ void k_sufrow()
{
    const int kb = blockIdx.x;           // 0..NQB-1
    const int z  = blockIdx.y;
    const int d  = threadIdx.x;          // 0..127
    const int b = z >> 4, h = z & 15;
    float acc = g_suf[((size_t)z * NQB + kb) * HD + d];
    const bf* Vb = g_vh + ((size_t)b * SEQ + kb * 64) * EMB + h * HD + d;
    float* Sr = g_sufr + ((size_t)z * SEQ + kb * 64) * HD + d;
    for (int r = 63; r >= 0; r--) {
        Sr[(size_t)r * HD] = acc;
        acc += __bfloat162float(Vb[(size_t)r * EMB]);
    }
}

// ---------------- PV (tmin-free): N = sum_{j<=i} t_ij V_j (diag mask -> 0) --------
#define PV_P_LD   72
#define PV_V_LD   136
#define PV_PBYTES (128 * PV_P_LD * 2)
#define PV_VBYTES (64 * PV_V_LD * 2)
#define PV_STAGEB (PV_PBYTES + PV_VBYTES)
#define PV_SMEM   (2 * PV_STAGEB)         // 71680

__global__ __launch_bounds__(256, 2) void k_pv(int zb)
{
    extern __shared__ char dsm[];
    const uint32_t sb = smem_u32(dsm);

    const int qb = (gridDim.x - 1) - blockIdx.x;
    const int z  = zb + blockIdx.y;
    const int b = z >> 4, h = z & 15;
    const int tid  = threadIdx.x;
    const int wid  = tid >> 5;
    const int lane = tid & 31;

    const bf* Sb = (const bf*)g_S + (size_t)z * SEQ * SEQ;
    const bf* Vh = g_vh + (size_t)b * SEQ * EMB + h * HD;

    const int m0 = (wid >> 2) * 64;
    const int n0 = (wid & 3) * 32;
    const int alr = lane & 15;
    const int alc = (lane >> 4) * 8;
    const int l15 = lane & 15;

    float acc[4][4][4];
#pragma unroll
    for (int i = 0; i < 4; i++)
#pragma unroll
        for (int j = 0; j < 4; j++)
#pragma unroll
            for (int c = 0; c < 4; c++) acc[i][j][c] = 0.f;

    auto issueT = [&](int ck) {
        const int c0 = ck * 64;
        const uint32_t so = sb + (ck & 1) * PV_STAGEB;
#pragma unroll
        for (int l = 0; l < 4; l++) {
            const int v = tid + l * 256;
            {   const int r = v >> 3; const int ce = (v & 7) * 8;
                cp16(so + r * (PV_P_LD * 2) + ce * 2,
                     Sb + (size_t)(qb * 128 + r) * SEQ + c0 + ce); }
            {   const int r = v >> 4; const int ce = (v & 15) * 8;
                cp16(so + PV_PBYTES + r * (PV_V_LD * 2) + ce * 2,
                     Vh + (size_t)(c0 + r) * EMB + ce); }
        }
    };
    auto domma = [&](int stage) {
        const uint32_t pP = sb + stage * PV_STAGEB;
        const uint32_t pV = pP + PV_PBYTES;
#pragma unroll
        for (int ks = 0; ks < 64; ks += 16) {
            uint32_t fA[4][4], fB[4][2];
#pragma unroll
            for (int i = 0; i < 4; i++)
                ldsm_x4(fA[i], pP + (m0 + 16 * i + alr) * (PV_P_LD * 2) + (ks + alc) * 2);
#pragma unroll
            for (int j = 0; j < 4; j++)
                ldsm_x2t(fB[j], pV + (ks + l15) * (PV_V_LD * 2) + (n0 + 8 * j) * 2);
#pragma unroll
            for (int i = 0; i < 4; i++)
#pragma unroll
                for (int j = 0; j < 4; j++)
                    mma16816(acc[i][j], fA[i], fB[j]);
        }
    };

    const int nfull = 2 * qb;
    if (nfull > 0) issueT(0);
    cp_commit();
    for (int ck = 0; ck < nfull; ck++) {
        cp_wait<0>();
        __syncthreads();
        if (ck + 1 < nfull) issueT(ck + 1);
        cp_commit();
        domma(ck & 1);
    }
    // diagonal 2 chunks: masked positions contribute 0 (handled analytically later)
#pragma unroll
    for (int dk = 0; dk < 2; dk++) {
        const int ck = nfull + dk;
        const int c0 = ck * 64;
        const int stage = ck & 1;
        bf* sP = (bf*)(dsm + stage * PV_STAGEB);
        bf* sV = (bf*)(dsm + stage * PV_STAGEB + PV_PBYTES);
        __syncthreads();
#pragma unroll
        for (int l = 0; l < 4; l++) {
            const int v = tid + l * 256;
            const int r = v >> 3;
            const int c8 = (v & 7) * 8;
            const int ig = qb * 128 + r;
            const int jg = c0 + c8;
            union { uint4 u; ushort e[8]; } w;
            w.u = *(const uint4*)(Sb + (size_t)ig * SEQ + jg);
#pragma unroll
            for (int e = 0; e < 8; e++)
                if (jg + e > ig) w.e[e] = 0;
            *(uint4*)(sP + r * PV_P_LD + c8) = w.u;
        }
#pragma unroll
        for (int l = 0; l < 4; l++) {
            const int v = tid + l * 256;
            const int r = v >> 4;
            const int c8 = (v & 15) * 8;
            *(uint4*)(sV + r * PV_V_LD + c8) = *(const uint4*)(Vh + (size_t)(c0 + r) * EMB + c8);
        }
        __syncthreads();
        domma(stage);
    }

    // epilogue: write raw fp32 numerator
    const int g  = lane >> 2;
    const int tc = (lane & 3) * 2;
    float* Np = g_N + ((size_t)b * SEQ + qb * 128) * EMB + h * HD;
#pragma unroll
    for (int i = 0; i < 4; i++) {
        const int r0 = m0 + 16 * i + g;
        const int r8 = r0 + 8;
#pragma unroll
        for (int j = 0; j < 4; j++) {
            const int gc = n0 + 8 * j + tc;
            float2 v0 = {acc[i][j][0], acc[i][j][1]};
            float2 v1 = {acc[i][j][2], acc[i][j][3]};
            *(float2*)(Np + (size_t)r0 * EMB + gc) = v0;
            *(float2*)(Np + (size_t)r8 * EMB + gc) = v1;
        }
    }
}

// ---------------- fixo: O = (N + tot + tmin*sufr) / Z, split to bf16 hi/lo --------
__global__ void k_fixo(int zb)
{
    const int i = blockIdx.x;            // row within seq
    const int z = zb + blockIdx.y;
    const int b = z >> 4, h = z & 15;
    const int d = threadIdx.x;           // 0..127
    const float tmin = key2f(g_min_key);
    const float Zr = g_z[z * SEQ + i] + (float)(SEQ - 1 - i) * (1.f + tmin);
    const float inv = 1.f / Zr;
    const size_t o = ((size_t)b * SEQ + i) * EMB + h * HD + d;
    const float n = g_N[o] + g_tot[z * HD + d]
                  + tmin * g_sufr[((size_t)z * SEQ + i) * HD + d];
    const float ov = n * inv;
    const bf hh = __float2bfloat16(ov);
    g_xh[o] = hh;
    g_xl[o] = __float2bfloat16(ov - __bfloat162float(hh));
}

// ---------------- launch: multi-stream DAG with scores/PV/fixo pipelining ---------
extern "C" void kernel_launch(void* const* d_in, const int* in_sizes, int n_in,
                              void* d_out, int out_size)
{
    (void)in_sizes; (void)n_in; (void)out_size;
    const float* x  = (const float*)d_in[0];
    const float* wq = (const float*)d_in[1];
    const float* wk = (const float*)d_in[2];
    const float* wv = (const float*)d_in[3];
    const float* wo = (const float*)d_in[4];
    const float* bo = (const float*)d_in[5];
    float* out = (float*)d_out;

    cudaFuncSetAttribute(k_mma_t<1>, cudaFuncAttributeMaxDynamicSharedMemorySize, MMA_SMEM_1);
    cudaFuncSetAttribute(k_mma_t<3>, cudaFuncAttributeMaxDynamicSharedMemorySize, MMA_SMEM_3);
    cudaFuncSetAttribute(k_pv, cudaFuncAttributeMaxDynamicSharedMemorySize, PV_SMEM);

    void *pS;
    void *pxh, *pxl, *pwqh, *pwkh, *pwvh, *pwvl, *pwoh, *pwol;
    void *pqh, *pkh, *pvh;
    cudaGetSymbolAddress(&pS,  g_S);
    cudaGetSymbolAddress(&pxh, g_xh);  cudaGetSymbolAddress(&pxl, g_xl);
    cudaGetSymbolAddress(&pwqh, g_wqh);
    cudaGetSymbolAddress(&pwkh, g_wkh);
    cudaGetSymbolAddress(&pwvh, g_wvh); cudaGetSymbolAddress(&pwvl, g_wvl);
    cudaGetSymbolAddress(&pwoh, g_woh); cudaGetSymbolAddress(&pwol, g_wol);
    cudaGetSymbolAddress(&pqh, g_qh);  cudaGetSymbolAddress(&pkh, g_kh);
    cudaGetSymbolAddress(&pvh, g_vh);

    cudaStream_t s1 = g_hx.s1, s2 = g_hx.s2, s3 = g_hx.s3;
    dim3 tg(64, 64), tb(32, 8);
    dim3 gqk(EMB / 128, MROWS / 128, 2);
    dim3 gproj(EMB / 128, MROWS / 128, 1);
    dim3 gscg(SEQ / 128, SEQ / 128, ZPG);    // per-group scores (16,16,8)

    // origin: init, x split
    k_init<<<512, 256>>>();
    cudaEventRecord(g_hx.eI, 0);
    k_split<<<(MROWS * EMB) / 2048, 256>>>(x, (bf*)pxh, (bf*)pxl);
    cudaEventRecord(g_hx.eX, 0);

    // s1: wq + wk splits -> merged QK projection
    cudaStreamWaitEvent(s1, g_hx.eI, 0);
    k_splitwT<<<tg, tb, 0, s1>>>(wq, (bf*)pwqh, nullptr);
    k_splitwT<<<tg, tb, 0, s1>>>(wk, (bf*)pwkh, nullptr);
    cudaStreamWaitEvent(s1, g_hx.eX, 0);
    k_mma_t<1><<<gqk, 256, MMA_SMEM_1, s1>>>((bf*)pxh, nullptr, (bf*)pwqh, nullptr,
        EMB, EMB, EMB, 4, 0, nullptr, (bf*)pqh, nullptr, (bf*)pwkh, (bf*)pkh);
    cudaEventRecord(g_hx.eQK, s1);

    // s2: wo split (then reused for PV groups)
    cudaStreamWaitEvent(s2, g_hx.eI, 0);
    k_splitwT<<<tg, tb, 0, s2>>>(wo, (bf*)pwoh, (bf*)pwol);
    cudaEventRecord(g_hx.eWo, s2);

    // s3: wv split -> V proj (fused block sums) -> suffix scans (then fixo groups)
    cudaStreamWaitEvent(s3, g_hx.eI, 0);
    k_splitwT<<<tg, tb, 0, s3>>>(wv, (bf*)pwvh, (bf*)pwvl);
    cudaStreamWaitEvent(s3, g_hx.eX, 0);
    k_mma_t<3><<<gproj, 256, MMA_SMEM_3, s3>>>((bf*)pxh, (bf*)pxl, (bf*)pwvh, (bf*)pwvl,
        EMB, EMB, EMB, 7, 0, nullptr, (bf*)pvh, nullptr, nullptr, nullptr);
    k_sufv2<<<NBH, HD, 0, s3>>>();
    k_sufrow<<<dim3(NQB, NBH), HD, 0, s3>>>();
    cudaEventRecord(g_hx.eV, s3);

    // origin: scores in NGRP head-groups (sequential), PV(g) pipelined on s2
    cudaStreamWaitEvent(0, g_hx.eQK, 0);
    for (int g = 0; g < NGRP; g++) {
        k_mma_t<1><<<gscg, 256, MMA_SMEM_1>>>((bf*)pqh, nullptr, (bf*)pkh, nullptr,
            EMB, EMB, HD, 6, g * ZPG, nullptr, (bf*)pS, nullptr, nullptr, nullptr);
        cudaEventRecord(g_hx.eS[g], 0);

        cudaStreamWaitEvent(s2, g_hx.eS[g], 0);
        if (g == 0) cudaStreamWaitEvent(s2, g_hx.eV, 0);
        k_pv<<<dim3(SEQ / 128, ZPG), 256, PV_SMEM, s2>>>(g * ZPG);
        cudaEventRecord(g_hx.ePV[g], s2);
    }

    // fixo(g) on s3: needs PV(g) + tmin (all scores)
    cudaStreamWaitEvent(s3, g_hx.eS[NGRP - 1], 0);
    for (int g = 0; g < NGRP; g++) {
        cudaStreamWaitEvent(s3, g_hx.ePV[g], 0);
        k_fixo<<<dim3(SEQ, ZPG), HD, 0, s3>>>(g * ZPG);
        cudaEventRecord(g_hx.eF[g], s3);
    }

    // origin: output projection after all fixo
    for (int g = 0; g < NGRP; g++) cudaStreamWaitEvent(0, g_hx.eF[g], 0);
    cudaStreamWaitEvent(0, g_hx.eWo, 0);
    k_mma_t<3><<<gproj, 256, MMA_SMEM_3>>>((bf*)pxh, (bf*)pxl, (bf*)pwoh, (bf*)pwol,
        EMB, EMB, EMB, 3, 0, out, nullptr, bo, nullptr, nullptr);
}